// round 2
// baseline (speedup 1.0000x reference)
#include <cuda_runtime.h>
#include <cuda_bf16.h>

#define CCH 256        // channels
#define LV 2           // levels
#define NP 4           // points
#define NOFF 16        // offset outputs (LV*NP*2)
#define NAW 8          // attn outputs (LV*NP)
#define NOUT 24        // total projection outputs
#define WPB 8          // warps per block

__global__ __launch_bounds__(WPB * 32)
void deform_attn_kernel(
    const float* __restrict__ query,        // [Q, C]
    const float* __restrict__ value,        // [Lv, Nv, C]
    const float* __restrict__ refpts,       // [Q, Lv, 2]
    const int*   __restrict__ shapes_raw,   // [Lv, 2] as int32 OR int64 (detected)
    const float* __restrict__ W_off,        // [C, 16]
    const float* __restrict__ b_off,        // [16]
    const float* __restrict__ W_attn,       // [C, 8]
    const float* __restrict__ b_attn,       // [8]
    float* __restrict__ out,                // [Q, C]
    int Q)
{
    // Shared: W transposed to [24][256] so the projection phase (strided
    // channel mapping, c = lane + 32k) reads stride-1 across lanes -> no
    // bank conflicts.
    __shared__ float wsh[NOUT * CCH];
    __shared__ int ssh[2 * LV];   // decoded (H, W) per level

    const int tid = threadIdx.x;
    if (tid == 0) {
        // int64 little-endian with small positive values -> odd int32 slots are 0.
        const bool is64 = (shapes_raw[1] == 0);
        for (int l = 0; l < LV; l++) {
            if (is64) {
                ssh[2 * l + 0] = shapes_raw[4 * l + 0];  // H
                ssh[2 * l + 1] = shapes_raw[4 * l + 2];  // W
            } else {
                ssh[2 * l + 0] = shapes_raw[2 * l + 0];
                ssh[2 * l + 1] = shapes_raw[2 * l + 1];
            }
        }
    }
    for (int idx = tid; idx < CCH * NOFF; idx += WPB * 32) {
        int c = idx >> 4, j = idx & 15;          // W_off is [C,16] row-major
        wsh[j * CCH + c] = W_off[idx];
    }
    for (int idx = tid; idx < CCH * NAW; idx += WPB * 32) {
        int c = idx >> 3, j = idx & 7;           // W_attn is [C,8] row-major
        wsh[(NOFF + j) * CCH + c] = W_attn[idx];
    }
    __syncthreads();

    const int warp = tid >> 5;
    const int lane = tid & 31;
    const int q = blockIdx.x * WPB + warp;
    if (q >= Q) return;

    // ---------------- Projection: p[j] = query[q] . W[:, j] ----------------
    float p[NOUT];
#pragma unroll
    for (int j = 0; j < NOUT; j++) p[j] = 0.f;

    const float* qrow = query + (size_t)q * CCH;
#pragma unroll
    for (int k = 0; k < CCH / 32; k++) {
        const int c = lane + k * 32;
        const float qv = __ldg(qrow + c);
#pragma unroll
        for (int j = 0; j < NOUT; j++)
            p[j] = fmaf(qv, wsh[j * CCH + c], p[j]);
    }
    // Butterfly reduce each of the 24 partial sums across the warp.
#pragma unroll
    for (int off = 16; off > 0; off >>= 1) {
#pragma unroll
        for (int j = 0; j < NOUT; j++)
            p[j] += __shfl_xor_sync(0xffffffffu, p[j], off);
    }
#pragma unroll
    for (int j = 0; j < NOFF; j++) p[j] += __ldg(b_off + j);
#pragma unroll
    for (int j = 0; j < NAW; j++) p[NOFF + j] += __ldg(b_attn + j);

    // ---------------- Softmax over the 8 attention logits -------------------
    float m = p[NOFF];
#pragma unroll
    for (int j = 1; j < NAW; j++) m = fmaxf(m, p[NOFF + j]);
    float aw[NAW];
    float ssum = 0.f;
#pragma unroll
    for (int j = 0; j < NAW; j++) {
        aw[j] = __expf(p[NOFF + j] - m);
        ssum += aw[j];
    }
    const float inv = 1.f / ssum;

    // ---------------- Bilinear sampling + weighted accumulation -------------
    // Vectorized channel mapping: lane owns channels [lane*8, lane*8+8).
    float4 acc0 = make_float4(0.f, 0.f, 0.f, 0.f);
    float4 acc1 = make_float4(0.f, 0.f, 0.f, 0.f);

    const float* ref = refpts + (size_t)q * (LV * 2);
    size_t loff = 0;

#pragma unroll
    for (int l = 0; l < LV; l++) {
        const int Hs = ssh[2 * l + 0];
        const int Ws = ssh[2 * l + 1];
        const float fW = (float)Ws, fH = (float)Hs;
        const float rx = __ldg(ref + l * 2 + 0);
        const float ry = __ldg(ref + l * 2 + 1);
        const float* vb = value + loff;

#pragma unroll
        for (int pt = 0; pt < NP; pt++) {
            const float ox = p[l * (NP * 2) + pt * 2 + 0];
            const float oy = p[l * (NP * 2) + pt * 2 + 1];
            const float a  = aw[l * NP + pt] * inv;

            const float lx = rx + ox / fW;
            const float ly = ry + oy / fH;
            const float ix = lx * fW - 0.5f;
            const float iy = ly * fH - 0.5f;
            const float x0f = floorf(ix);
            const float y0f = floorf(iy);
            const int x0 = (int)x0f;
            const int y0 = (int)y0f;
            const float fx = ix - x0f;
            const float fy = iy - y0f;

            const float w00 = (1.f - fx) * (1.f - fy) * a;
            const float w01 = fx * (1.f - fy) * a;
            const float w10 = (1.f - fx) * fy * a;
            const float w11 = fx * fy * a;

            const int xs[2] = {x0, x0 + 1};
            const int ys[2] = {y0, y0 + 1};
            const float ws[4] = {w00, w01, w10, w11};

#pragma unroll
            for (int cy = 0; cy < 2; cy++) {
#pragma unroll
                for (int cx = 0; cx < 2; cx++) {
                    const int xx = xs[cx];
                    const int yy = ys[cy];
                    const float w = ws[cy * 2 + cx];
                    if (xx >= 0 && xx < Ws && yy >= 0 && yy < Hs) {
                        const float4* vp = (const float4*)(vb + ((size_t)yy * Ws + xx) * CCH);
                        const float4 v0 = __ldg(vp + lane * 2 + 0);
                        const float4 v1 = __ldg(vp + lane * 2 + 1);
                        acc0.x = fmaf(w, v0.x, acc0.x);
                        acc0.y = fmaf(w, v0.y, acc0.y);
                        acc0.z = fmaf(w, v0.z, acc0.z);
                        acc0.w = fmaf(w, v0.w, acc0.w);
                        acc1.x = fmaf(w, v1.x, acc1.x);
                        acc1.y = fmaf(w, v1.y, acc1.y);
                        acc1.z = fmaf(w, v1.z, acc1.z);
                        acc1.w = fmaf(w, v1.w, acc1.w);
                    }
                }
            }
        }
        loff += (size_t)Hs * (size_t)Ws * CCH;
    }

    float4* op = (float4*)(out + (size_t)q * CCH);
    op[lane * 2 + 0] = acc0;
    op[lane * 2 + 1] = acc1;
}

extern "C" void kernel_launch(void* const* d_in, const int* in_sizes, int n_in,
                              void* d_out, int out_size)
{
    const float* query   = (const float*)d_in[0];
    // d_in[1] = key (unused)
    const float* value   = (const float*)d_in[2];
    const float* refpts  = (const float*)d_in[3];
    const int*   shapes  = (const int*)d_in[4];
    const float* W_off   = (const float*)d_in[5];
    const float* b_off   = (const float*)d_in[6];
    const float* W_attn  = (const float*)d_in[7];
    const float* b_attn  = (const float*)d_in[8];
    float*       out     = (float*)d_out;

    const int Q = in_sizes[0] / CCH;
    const int blocks = (Q + WPB - 1) / WPB;
    deform_attn_kernel<<<blocks, WPB * 32>>>(
        query, value, refpts, shapes, W_off, b_off, W_attn, b_attn, out, Q);
}